// round 7
// baseline (speedup 1.0000x reference)
#include <cuda_runtime.h>
#include <math_constants.h>

// Causal sliding-window min, W = 128 == segment size (van Herk / Gil-Werman).
// out[seg g, p] = min(pref_g[p], suf_{g-1}[p+1]),  suf[128] := +inf.
//
// Warp-per-segment, 4 elems/lane, SEGW=4 contiguous segments per warp plus a
// redundantly loaded halo segment (suffix only). Register-resident suffix
// handoff. Segments processed in PAIRS with their shfl_xor butterflies
// interleaved (two independent chains in flight) to halve exposed SHFL
// latency. __launch_bounds__(128,12) caps regs at 42 -> 48 warps/SM.

#define WSZ     128
#define NWARPS  4
#define BLOCK   (NWARPS * 32)     // 128 threads
#define SEGW    4                 // segments per warp
#define SEGS    (NWARPS * SEGW)   // 16 segments per CTA
#define TILE    (SEGS * WSZ)      // 2048 elements per CTA
#define MINCTAS 12

__device__ __forceinline__ float4 ld_guard(const float* __restrict__ x,
                                           int base, int n)
{
    const float INF = CUDART_INF_F;
    float4 v;
    v.x = (base >= 0 && base + 0 < n) ? x[base + 0] : INF;
    v.y = (base >= 0 && base + 1 < n) ? x[base + 1] : INF;
    v.z = (base >= 0 && base + 2 < n) ? x[base + 2] : INF;
    v.w = (base >= 0 && base + 3 < n) ? x[base + 3] : INF;
    return v;
}

template<bool SAFE>
__device__ __forceinline__ void run_warp(const float* __restrict__ x,
                                         float* __restrict__ out,
                                         int wbase, int n, int lane)
{
    const float INF = CUDART_INF_F;

    // ---- front-batched loads: halo + 4 segments (MLP = 5) ----
    float4 vh = SAFE ? *(const float4*)(x + (wbase - WSZ))
                     : ld_guard(x, wbase - WSZ, n);
    float4 vr[SEGW];
    #pragma unroll
    for (int k = 0; k < SEGW; k++)
        vr[k] = SAFE ? *(const float4*)(x + (wbase + k * WSZ))
                     : ld_guard(x, wbase + k * WSZ, n);

    // ---- halo: suffix handoff registers ----
    float ps1, ps2, ps3, psc;
    {
        float s2 = fminf(vh.z, vh.w);
        float s1 = fminf(vh.y, s2);
        float s0 = fminf(vh.x, s1);
        float B = s0, A = s0;                // backward-only butterfly
        #pragma unroll
        for (int d = 1; d < 32; d <<= 1) {
            float Ap = __shfl_xor_sync(0xffffffffu, A, d);
            if (!(lane & d)) B = fminf(B, Ap);
            A = fminf(A, Ap);
        }
        float sc = __shfl_down_sync(0xffffffffu, B, 1);
        if (lane == 31) sc = INF;
        ps1 = fminf(s1, sc);
        ps2 = fminf(s2, sc);
        ps3 = fminf(vh.w, sc);
        psc = sc;
    }

    // ---- segment pairs with interleaved butterflies ----
    #pragma unroll
    for (int pr = 0; pr < SEGW / 2; pr++) {
        const float4 va = vr[2 * pr + 0];
        const float4 vb = vr[2 * pr + 1];

        // local prefix + suffix chains (4 independent chains)
        float pa1 = fminf(va.y, va.x);
        float pa2 = fminf(va.z, pa1);
        float pa3 = fminf(va.w, pa2);
        float sa2 = fminf(va.z, va.w);
        float sa1 = fminf(va.y, sa2);
        float sa0 = fminf(va.x, sa1);

        float pb1 = fminf(vb.y, vb.x);
        float pb2 = fminf(vb.z, pb1);
        float pb3 = fminf(vb.w, pb2);
        float sb2 = fminf(vb.z, vb.w);
        float sb1 = fminf(vb.y, sb2);
        float sb0 = fminf(vb.x, sb1);

        // two interleaved bidirectional butterflies (independent A-chains)
        float Fa = sa0, Ba = sa0, Aa = sa0;
        float Fb = sb0, Bb = sb0, Ab = sb0;
        #pragma unroll
        for (int d = 1; d < 32; d <<= 1) {
            float Aap = __shfl_xor_sync(0xffffffffu, Aa, d);
            float Abp = __shfl_xor_sync(0xffffffffu, Ab, d);
            if (lane & d) { Fa = fminf(Fa, Aap); Fb = fminf(Fb, Abp); }
            else          { Ba = fminf(Ba, Aap); Bb = fminf(Bb, Abp); }
            Aa = fminf(Aa, Aap); Ab = fminf(Ab, Abp);
        }
        float pca = __shfl_up_sync(0xffffffffu, Fa, 1);
        float pcb = __shfl_up_sync(0xffffffffu, Fb, 1);
        float sca = __shfl_down_sync(0xffffffffu, Ba, 1);
        float scb = __shfl_down_sync(0xffffffffu, Bb, 1);
        if (lane == 0)  { pca = INF; pcb = INF; }
        if (lane == 31) { sca = INF; scb = INF; }

        // combine segment a with handoff from previous segment
        {
            float e0 = fminf(fminf(va.x, pca), ps1);
            float e1 = fminf(fminf(pa1,  pca), ps2);
            float e2 = fminf(fminf(pa2,  pca), ps3);
            float e3 = fminf(fminf(pa3,  pca), psc);
            int base = wbase + (2 * pr + 0) * WSZ;
            if (SAFE) {
                __stcs((float4*)(out + base), make_float4(e0, e1, e2, e3));
            } else if (base >= 0 && base < n) {
                out[base] = e0;
                if (base + 1 < n) out[base + 1] = e1;
                if (base + 2 < n) out[base + 2] = e2;
                if (base + 3 < n) out[base + 3] = e3;
            }
        }

        // handoff a -> b, combine segment b
        {
            float qa1 = fminf(sa1,  sca);
            float qa2 = fminf(sa2,  sca);
            float qa3 = fminf(va.w, sca);
            float e0 = fminf(fminf(vb.x, pcb), qa1);
            float e1 = fminf(fminf(pb1,  pcb), qa2);
            float e2 = fminf(fminf(pb2,  pcb), qa3);
            float e3 = fminf(fminf(pb3,  pcb), sca);
            int base = wbase + (2 * pr + 1) * WSZ;
            if (SAFE) {
                __stcs((float4*)(out + base), make_float4(e0, e1, e2, e3));
            } else if (base >= 0 && base < n) {
                out[base] = e0;
                if (base + 1 < n) out[base + 1] = e1;
                if (base + 2 < n) out[base + 2] = e2;
                if (base + 3 < n) out[base + 3] = e3;
            }
        }

        // handoff b -> next pair
        ps1 = fminf(sb1,  scb);
        ps2 = fminf(sb2,  scb);
        ps3 = fminf(vb.w, scb);
        psc = scb;
    }
}

__global__ __launch_bounds__(BLOCK, MINCTAS)
void swmin128_kernel(const float* __restrict__ x,
                     float* __restrict__ out,
                     int n)
{
    const int lane = threadIdx.x & 31;
    const int wid  = threadIdx.x >> 5;
    const int wseg  = blockIdx.x * SEGS + wid * SEGW;
    const int wbase = wseg * WSZ + lane * 4;

    const bool safe = (wseg >= 1) && ((wseg + SEGW) * WSZ <= n);
    if (safe) run_warp<true >(x, out, wbase, n, lane);
    else      run_warp<false>(x, out, wbase, n, lane);
}

extern "C" void kernel_launch(void* const* d_in, const int* in_sizes, int n_in,
                              void* d_out, int out_size)
{
    const float* x = (const float*)d_in[0];
    float* out = (float*)d_out;
    int n = in_sizes[0];
    int grid = (n + TILE - 1) / TILE;   // 4096 for N = 8,388,608
    swmin128_kernel<<<grid, BLOCK>>>(x, out, n);
}

// round 9
// speedup vs baseline: 1.0201x; 1.0201x over previous
#include <cuda_runtime.h>
#include <math_constants.h>

// Causal sliding-window min, W = 128 == segment size (van Herk / Gil-Werman).
// out[seg g, p] = min(pref_g[p], suf_{g-1}[p+1]),  suf[128] := +inf.
//
// Warp-per-segment, 4 elems/lane, SEGW=8 contiguous segments per warp plus a
// redundantly loaded halo segment (suffix only; 12.5% overhead).
// Register-resident suffix handoff: lane l needs suf_prev at 4l+1..4l+4 =
// {ps1,ps2,ps3,psc}. Segments processed in PAIRS with interleaved shfl_xor
// butterflies (two independent chains in flight). Warp-uniform SAFE split
// removes all bounds checks from interior warps.

#define WSZ     128
#define NWARPS  8
#define BLOCK   (NWARPS * 32)     // 256 threads
#define SEGW    8                 // segments per warp
#define SEGS    (NWARPS * SEGW)   // 64 segments per CTA
#define TILE    (SEGS * WSZ)      // 8192 elements per CTA

__device__ __forceinline__ float4 ld_guard(const float* __restrict__ x,
                                           int base, int n)
{
    const float INF = CUDART_INF_F;
    float4 v;
    v.x = (base >= 0 && base + 0 < n) ? x[base + 0] : INF;
    v.y = (base >= 0 && base + 1 < n) ? x[base + 1] : INF;
    v.z = (base >= 0 && base + 2 < n) ? x[base + 2] : INF;
    v.w = (base >= 0 && base + 3 < n) ? x[base + 3] : INF;
    return v;
}

template<bool SAFE>
__device__ __forceinline__ void run_warp(const float* __restrict__ x,
                                         float* __restrict__ out,
                                         int wbase, int n, int lane)
{
    const float INF = CUDART_INF_F;

    // ---- front-batched loads: halo + 8 segments (MLP = 9) ----
    float4 vh = SAFE ? *(const float4*)(x + (wbase - WSZ))
                     : ld_guard(x, wbase - WSZ, n);
    float4 vr[SEGW];
    #pragma unroll
    for (int k = 0; k < SEGW; k++)
        vr[k] = SAFE ? *(const float4*)(x + (wbase + k * WSZ))
                     : ld_guard(x, wbase + k * WSZ, n);

    // ---- halo: suffix handoff registers ----
    float ps1, ps2, ps3, psc;
    {
        float s2 = fminf(vh.z, vh.w);
        float s1 = fminf(vh.y, s2);
        float s0 = fminf(vh.x, s1);
        float B = s0, A = s0;                // backward-only butterfly
        #pragma unroll
        for (int d = 1; d < 32; d <<= 1) {
            float Ap = __shfl_xor_sync(0xffffffffu, A, d);
            if (!(lane & d)) B = fminf(B, Ap);
            if (d < 16)      A = fminf(A, Ap);
        }
        float sc = __shfl_down_sync(0xffffffffu, B, 1);
        if (lane == 31) sc = INF;
        ps1 = fminf(s1, sc);
        ps2 = fminf(s2, sc);
        ps3 = fminf(vh.w, sc);
        psc = sc;
    }

    // ---- segment pairs with interleaved butterflies ----
    #pragma unroll
    for (int pr = 0; pr < SEGW / 2; pr++) {
        const float4 va = vr[2 * pr + 0];
        const float4 vb = vr[2 * pr + 1];

        // local prefix + suffix chains (4 independent chains)
        float pa1 = fminf(va.y, va.x);
        float pa2 = fminf(va.z, pa1);
        float sa2 = fminf(va.z, va.w);
        float sa1 = fminf(va.y, sa2);
        float sa0 = fminf(va.x, sa1);        // lane min of a

        float pb1 = fminf(vb.y, vb.x);
        float pb2 = fminf(vb.z, pb1);
        float sb2 = fminf(vb.z, vb.w);
        float sb1 = fminf(vb.y, sb2);
        float sb0 = fminf(vb.x, sb1);        // lane min of b

        // two interleaved bidirectional butterflies (independent chains)
        float Fa = sa0, Ba = sa0, Aa = sa0;
        float Fb = sb0, Bb = sb0, Ab = sb0;
        #pragma unroll
        for (int d = 1; d < 32; d <<= 1) {
            float Aap = __shfl_xor_sync(0xffffffffu, Aa, d);
            float Abp = __shfl_xor_sync(0xffffffffu, Ab, d);
            if (lane & d) { Fa = fminf(Fa, Aap); Fb = fminf(Fb, Abp); }
            else          { Ba = fminf(Ba, Aap); Bb = fminf(Bb, Abp); }
            if (d < 16)   { Aa = fminf(Aa, Aap); Ab = fminf(Ab, Abp); }
        }
        float pca = __shfl_up_sync(0xffffffffu, Fa, 1);
        float pcb = __shfl_up_sync(0xffffffffu, Fb, 1);
        float sca = __shfl_down_sync(0xffffffffu, Ba, 1);
        float scb = __shfl_down_sync(0xffffffffu, Bb, 1);
        if (lane == 0)  { pca = INF; pcb = INF; }
        if (lane == 31) { sca = INF; scb = INF; }

        // combine segment a with handoff from previous segment
        {
            float e0 = fminf(fminf(va.x, pca), ps1);
            float e1 = fminf(fminf(pa1,  pca), ps2);
            float e2 = fminf(fminf(pa2,  pca), ps3);
            float e3 = fminf(Fa, psc);       // Fa == full inclusive prefix
            int base = wbase + (2 * pr + 0) * WSZ;
            if (SAFE) {
                __stcs((float4*)(out + base), make_float4(e0, e1, e2, e3));
            } else if (base >= 0 && base < n) {
                out[base] = e0;
                if (base + 1 < n) out[base + 1] = e1;
                if (base + 2 < n) out[base + 2] = e2;
                if (base + 3 < n) out[base + 3] = e3;
            }
        }

        // handoff a -> b, combine segment b
        {
            float qa1 = fminf(sa1,  sca);
            float qa2 = fminf(sa2,  sca);
            float qa3 = fminf(va.w, sca);
            float e0 = fminf(fminf(vb.x, pcb), qa1);
            float e1 = fminf(fminf(pb1,  pcb), qa2);
            float e2 = fminf(fminf(pb2,  pcb), qa3);
            float e3 = fminf(Fb, sca);       // Fb == full inclusive prefix
            int base = wbase + (2 * pr + 1) * WSZ;
            if (SAFE) {
                __stcs((float4*)(out + base), make_float4(e0, e1, e2, e3));
            } else if (base >= 0 && base < n) {
                out[base] = e0;
                if (base + 1 < n) out[base + 1] = e1;
                if (base + 2 < n) out[base + 2] = e2;
                if (base + 3 < n) out[base + 3] = e3;
            }
        }

        // handoff b -> next pair
        ps1 = fminf(sb1,  scb);
        ps2 = fminf(sb2,  scb);
        ps3 = fminf(vb.w, scb);
        psc = scb;
    }
}

__global__ __launch_bounds__(BLOCK)
void swmin128_kernel(const float* __restrict__ x,
                     float* __restrict__ out,
                     int n)
{
    const int lane = threadIdx.x & 31;
    const int wid  = threadIdx.x >> 5;
    const int wseg  = blockIdx.x * SEGS + wid * SEGW;
    const int wbase = wseg * WSZ + lane * 4;

    // warp-uniform safety: halo in-bounds below and all segments inside n
    const bool safe = (wseg >= 1) && ((wseg + SEGW) * WSZ <= n);
    if (safe) run_warp<true >(x, out, wbase, n, lane);
    else      run_warp<false>(x, out, wbase, n, lane);
}

extern "C" void kernel_launch(void* const* d_in, const int* in_sizes, int n_in,
                              void* d_out, int out_size)
{
    const float* x = (const float*)d_in[0];
    float* out = (float*)d_out;
    int n = in_sizes[0];
    int grid = (n + TILE - 1) / TILE;   // 1024 for N = 8,388,608
    swmin128_kernel<<<grid, BLOCK>>>(x, out, n);
}